// round 2
// baseline (speedup 1.0000x reference)
#include <cuda_runtime.h>
#include <math.h>
#include <stdint.h>

#define BATCH 8
#define NPTS  3136
#define PTOT  25088           /* BATCH*NPTS */
#define CA    96
#define CB    192
#define KNN   9

/* ------------------------------------------------------------------ */
/* scratch: __device__ globals (no allocations allowed)                */
/* all activation buffers are channel-major: buf[c*PTOT + b*NPTS + n]  */
/* ------------------------------------------------------------------ */
__device__ float g_Z1 [CA*PTOT];   /* fc1 pre-BN; later reused for fc2 pre-BN */
__device__ float g_H  [CA*PTOT];   /* post-BN1 features                        */
__device__ float g_XN [CA*PTOT];   /* L2-normalized features                   */
__device__ float g_sqn[PTOT];      /* ||xn||^2 per point                       */
__device__ float g_pv [PTOT*2*KNN];
__device__ int   g_pi [PTOT*2*KNN];
__device__ int   g_nn [PTOT*KNN];
__device__ float g_Y  [CB*PTOT];
__device__ float g_Z2 [CB*PTOT];
__device__ float g_Y2 [CB*PTOT];
__device__ float g_ps [CB*8];
__device__ float g_ps2[CB*8];
__device__ float g_al [CB];
__device__ float g_bt [CB];

/* ------------------------------------------------------------------ */
/* fc1: Z1[o][p] = sum_k W[o][k]*x[b][k][n] + b[o]                     */
/* grid 392 (=PTOT/64), block 256, dyn smem 61440B                     */
/* ------------------------------------------------------------------ */
__global__ __launch_bounds__(256) void k_fc1(const float* __restrict__ x,
                                             const float* __restrict__ W,
                                             const float* __restrict__ bias,
                                             float* __restrict__ Z1) {
    extern __shared__ float sm[];
    float* xs = sm;            /* [96][64]  k-major input tile   */
    float* ws = sm + 96 * 64;  /* [96][96]  natural W layout     */
    const int t  = threadIdx.x;
    const int p0 = blockIdx.x * 64;
    const int b  = p0 / NPTS;            /* 64 | 3136: no straddle */
    const int n0 = p0 - b * NPTS;

    for (int i = t; i < 96 * 64; i += 256) {
        int k = i >> 6, c = i & 63;
        xs[i] = x[(size_t)(b * CA + k) * NPTS + n0 + c];
    }
    for (int i = t; i < 96 * 96; i += 256) ws[i] = W[i];
    __syncthreads();

    const int og = t >> 4, pg = t & 15;  /* 16 out-groups x 16 point-groups */
    float acc[6][4];
    #pragma unroll
    for (int i = 0; i < 6; ++i) {
        float bb = bias[og * 6 + i];
        #pragma unroll
        for (int j = 0; j < 4; ++j) acc[i][j] = bb;
    }
    #pragma unroll 4
    for (int k = 0; k < 96; ++k) {
        float4 xv = *(const float4*)&xs[k * 64 + pg * 4];
        #pragma unroll
        for (int i = 0; i < 6; ++i) {
            float w = ws[(og * 6 + i) * 96 + k];
            acc[i][0] = fmaf(w, xv.x, acc[i][0]);
            acc[i][1] = fmaf(w, xv.y, acc[i][1]);
            acc[i][2] = fmaf(w, xv.z, acc[i][2]);
            acc[i][3] = fmaf(w, xv.w, acc[i][3]);
        }
    }
    #pragma unroll
    for (int i = 0; i < 6; ++i) {
        float4 v = make_float4(acc[i][0], acc[i][1], acc[i][2], acc[i][3]);
        *(float4*)&Z1[(size_t)(og * 6 + i) * PTOT + p0 + pg * 4] = v;
    }
}

/* ------------------------------------------------------------------ */
/* BN stats: deterministic two-level reduction over 25088 per channel  */
/* partial: grid (NC, 8), block 256                                    */
/* ------------------------------------------------------------------ */
__global__ __launch_bounds__(256) void k_stats_part(const float* __restrict__ Z) {
    __shared__ float ss[256], ss2[256];
    const int c  = blockIdx.x;
    const int ch = blockIdx.y;
    const float* row = Z + (size_t)c * PTOT + ch * NPTS;
    float s = 0.f, s2 = 0.f;
    for (int i = threadIdx.x; i < NPTS; i += 256) {
        float v = row[i];
        s += v; s2 += v * v;
    }
    ss[threadIdx.x] = s; ss2[threadIdx.x] = s2;
    __syncthreads();
    for (int o = 128; o > 0; o >>= 1) {
        if (threadIdx.x < o) {
            ss [threadIdx.x] += ss [threadIdx.x + o];
            ss2[threadIdx.x] += ss2[threadIdx.x + o];
        }
        __syncthreads();
    }
    if (threadIdx.x == 0) {
        g_ps [c * 8 + ch] = ss [0];
        g_ps2[c * 8 + ch] = ss2[0];
    }
}

__global__ void k_stats_fin(const float* __restrict__ gam,
                            const float* __restrict__ bet) {
    const int c = threadIdx.x;
    float s = 0.f, s2 = 0.f;
    #pragma unroll
    for (int h = 0; h < 8; ++h) { s += g_ps[c * 8 + h]; s2 += g_ps2[c * 8 + h]; }
    const float inv = 1.0f / (float)PTOT;
    float m = s * inv;
    float v = fmaxf(s2 * inv - m * m, 0.f);
    float a = gam[c] / sqrtf(v + 1e-5f);
    g_al[c] = a;
    g_bt[c] = bet[c] - m * a;
}

/* ------------------------------------------------------------------ */
/* apply BN1, write H; L2-normalize -> XN; squared norm of xn          */
/* grid 98, block 256 (one thread per point)                           */
/* ------------------------------------------------------------------ */
__global__ __launch_bounds__(256) void k_bnnorm() {
    __shared__ float sa[96], sb[96];
    const int t = threadIdx.x;
    if (t < 96) { sa[t] = g_al[t]; sb[t] = g_bt[t]; }
    __syncthreads();
    const int p = blockIdx.x * 256 + t;
    float s = 0.f;
    #pragma unroll 4
    for (int c = 0; c < 96; ++c) {
        float h = fmaf(sa[c], g_Z1[(size_t)c * PTOT + p], sb[c]);
        s += h * h;
    }
    const float rinv = 1.0f / fmaxf(sqrtf(s), 1e-12f);
    float s2 = 0.f;
    #pragma unroll 4
    for (int c = 0; c < 96; ++c) {
        float h = fmaf(sa[c], g_Z1[(size_t)c * PTOT + p], sb[c]);
        g_H[(size_t)c * PTOT + p] = h;
        float xn = h * rinv;
        g_XN[(size_t)c * PTOT + p] = xn;
        s2 += xn * xn;
    }
    g_sqn[p] = s2;
}

/* ------------------------------------------------------------------ */
/* KNN: fused Gram + top-9. grid (25, 8, 2), block 256                 */
/* score_m = ||xn_m||^2 - 2<xn_q,xn_m>  (same order as reference dist) */
/* smem: qs[96][128] + cs[96][64] + dots[128][68] + sq[64] = 108800 B  */
/* ------------------------------------------------------------------ */
#define QT 128
#define CT 64
#define DP 68
__global__ __launch_bounds__(256) void k_knn() {
    extern __shared__ float sm[];
    float* qs   = sm;               /* [96][QT] */
    float* cs   = qs + 96 * QT;     /* [96][CT] */
    float* dots = cs + 96 * CT;     /* [QT][DP] */
    float* sq   = dots + QT * DP;   /* [CT]     */

    const int t    = threadIdx.x;
    const int b    = blockIdx.y;
    const int q0   = blockIdx.x * QT;
    const int half = blockIdx.z;
    const int pb   = b * NPTS;

    for (int i = t; i < 96 * QT; i += 256) {
        int k = i >> 7, q = i & (QT - 1);
        int n = q0 + q; if (n >= NPTS) n = NPTS - 1;
        qs[i] = g_XN[(size_t)k * PTOT + pb + n];
    }

    float bv[KNN]; int bi[KNN];
    #pragma unroll
    for (int r = 0; r < KNN; ++r) { bv[r] = 3.4e38f; bi[r] = 0x7fffffff; }

    const int qg = t >> 4, cg = t & 15;
    const int qsel = t & (QT - 1);
    const int tile0 = half ? 25 : 0;
    const int tile1 = half ? 49 : 25;

    for (int tile = tile0; tile < tile1; ++tile) {
        const int cbase = tile * CT;
        __syncthreads();   /* previous phase-B reads of dots/sq done */
        for (int i = t; i < 96 * CT; i += 256) {
            int k = i >> 6, c = i & 63;
            cs[i] = g_XN[(size_t)k * PTOT + pb + cbase + c];
        }
        if (t < CT) sq[t] = g_sqn[pb + cbase + t];
        __syncthreads();

        /* gram: 8 queries x 4 candidates per thread */
        float acc[8][4];
        #pragma unroll
        for (int i = 0; i < 8; ++i)
            #pragma unroll
            for (int j = 0; j < 4; ++j) acc[i][j] = 0.f;

        #pragma unroll 4
        for (int k = 0; k < 96; ++k) {
            float4 qa = *(const float4*)&qs[k * QT + qg * 8];
            float4 qb = *(const float4*)&qs[k * QT + qg * 8 + 4];
            float4 cv = *(const float4*)&cs[k * CT + cg * 4];
            float qv[8] = {qa.x, qa.y, qa.z, qa.w, qb.x, qb.y, qb.z, qb.w};
            float cw[4] = {cv.x, cv.y, cv.z, cv.w};
            #pragma unroll
            for (int i = 0; i < 8; ++i)
                #pragma unroll
                for (int j = 0; j < 4; ++j)
                    acc[i][j] = fmaf(qv[i], cw[j], acc[i][j]);
        }
        #pragma unroll
        for (int i = 0; i < 8; ++i) {
            float4 v = make_float4(acc[i][0], acc[i][1], acc[i][2], acc[i][3]);
            *(float4*)&dots[(qg * 8 + i) * DP + cg * 4] = v;
        }
        __syncthreads();

        /* selection: one thread per query scans 64 candidates */
        if (t < QT) {
            #pragma unroll 4
            for (int c = 0; c < CT; ++c) {
                float s = fmaf(-2.f, dots[qsel * DP + c], sq[c]);
                int   j = cbase + c;
                if (s < bv[8] || (s == bv[8] && j < bi[8])) {
                    bv[8] = s; bi[8] = j;
                    #pragma unroll
                    for (int r = 8; r > 0; --r) {
                        bool sw = (bv[r] < bv[r-1]) ||
                                  (bv[r] == bv[r-1] && bi[r] < bi[r-1]);
                        if (sw) {
                            float tv = bv[r]; bv[r] = bv[r-1]; bv[r-1] = tv;
                            int   ti = bi[r]; bi[r] = bi[r-1]; bi[r-1] = ti;
                        }
                    }
                }
            }
        }
    }

    if (t < QT && q0 + qsel < NPTS) {
        size_t base = ((size_t)(pb + q0 + qsel) * 2 + half) * KNN;
        #pragma unroll
        for (int r = 0; r < KNN; ++r) { g_pv[base + r] = bv[r]; g_pi[base + r] = bi[r]; }
    }
}

/* ------------------------------------------------------------------ */
/* merge the two sorted partial top-9 lists (set only matters)         */
/* ------------------------------------------------------------------ */
__global__ void k_merge() {
    const int p = blockIdx.x * 256 + threadIdx.x;
    if (p >= PTOT) return;
    float va[KNN], vb[KNN]; int ja[KNN], jb[KNN];
    size_t base = (size_t)p * 2 * KNN;
    #pragma unroll
    for (int r = 0; r < KNN; ++r) {
        va[r] = g_pv[base + r];        ja[r] = g_pi[base + r];
        vb[r] = g_pv[base + KNN + r];  jb[r] = g_pi[base + KNN + r];
    }
    int ia = 0, ib = 0;
    #pragma unroll
    for (int r = 0; r < KNN; ++r) {
        float x1 = va[ia], x2 = vb[ib];
        int   i1 = ja[ia], i2 = jb[ib];
        bool pickA = (x1 < x2) || (x1 == x2 && i1 < i2);
        g_nn[(size_t)p * KNN + r] = pickA ? i1 : i2;
        if (pickA) ++ia; else ++ib;
    }
}

/* ------------------------------------------------------------------ */
/* max-relative aggregation + channel interleave                       */
/* y[2c][p] = h[c][p]; y[2c+1][p] = max_j h[c][nbr_j] - h[c][p]        */
/* grid (8, 13), block 256                                             */
/* ------------------------------------------------------------------ */
__global__ __launch_bounds__(256) void k_agg() {
    const int b = blockIdx.x;
    const int n = blockIdx.y * 256 + threadIdx.x;
    if (n >= NPTS) return;
    const int gp = b * NPTS + n;
    int nb[KNN];
    #pragma unroll
    for (int r = 0; r < KNN; ++r) nb[r] = b * NPTS + g_nn[(size_t)gp * KNN + r];
    for (int c = 0; c < 96; ++c) {
        const float* Hr = g_H + (size_t)c * PTOT;
        float hc = Hr[gp];
        float m = -3.4e38f;
        #pragma unroll
        for (int r = 0; r < KNN; ++r) m = fmaxf(m, Hr[nb[r]]);
        g_Y[(size_t)(2 * c)     * PTOT + gp] = hc;
        g_Y[(size_t)(2 * c + 1) * PTOT + gp] = m - hc;
    }
}

/* ------------------------------------------------------------------ */
/* generic K=192 GEMM: OUT[o][p] = sum_c W[o][c] IN[c][p] + b[o]       */
/* grid 392, block 256; k chunked by 48                                */
/* ------------------------------------------------------------------ */
template<int NCO>
__global__ __launch_bounds__(256) void k_gemm(const float* __restrict__ IN,
                                              const float* __restrict__ W,
                                              const float* __restrict__ bias,
                                              float* __restrict__ OUT) {
    extern __shared__ float sm[];
    float* ys = sm;            /* [48][64]   */
    float* ws = ys + 48 * 64;  /* [NCO][48]  */
    const int NO = NCO / 16;
    const int t  = threadIdx.x;
    const int p0 = blockIdx.x * 64;
    const int og = t >> 4, pg = t & 15;

    float acc[NO][4];
    #pragma unroll
    for (int i = 0; i < NO; ++i) {
        float bb = bias[og * NO + i];
        #pragma unroll
        for (int j = 0; j < 4; ++j) acc[i][j] = bb;
    }
    for (int kc = 0; kc < 4; ++kc) {
        __syncthreads();
        for (int i = t; i < 48 * 64; i += 256) {
            int k = i >> 6, c = i & 63;
            ys[i] = IN[(size_t)(kc * 48 + k) * PTOT + p0 + c];
        }
        for (int i = t; i < NCO * 48; i += 256) {
            int o = i / 48, k = i - o * 48;
            ws[i] = W[o * 192 + kc * 48 + k];
        }
        __syncthreads();
        #pragma unroll 4
        for (int k = 0; k < 48; ++k) {
            float4 yv = *(const float4*)&ys[k * 64 + pg * 4];
            #pragma unroll
            for (int i = 0; i < NO; ++i) {
                float w = ws[(og * NO + i) * 48 + k];
                acc[i][0] = fmaf(w, yv.x, acc[i][0]);
                acc[i][1] = fmaf(w, yv.y, acc[i][1]);
                acc[i][2] = fmaf(w, yv.z, acc[i][2]);
                acc[i][3] = fmaf(w, yv.w, acc[i][3]);
            }
        }
    }
    #pragma unroll
    for (int i = 0; i < NO; ++i) {
        float4 v = make_float4(acc[i][0], acc[i][1], acc[i][2], acc[i][3]);
        *(float4*)&OUT[(size_t)(og * NO + i) * PTOT + p0 + pg * 4] = v;
    }
}

/* ------------------------------------------------------------------ */
/* BN + exact GELU (erf), elementwise. grid (192, 98), block 256       */
/* ------------------------------------------------------------------ */
__global__ void k_bngelu(const float* __restrict__ Z, float* __restrict__ O) {
    const int c = blockIdx.x;
    const int i = blockIdx.y * 256 + threadIdx.x;
    const size_t id = (size_t)c * PTOT + i;
    float v = fmaf(g_al[c], Z[id], g_bt[c]);
    O[id] = 0.5f * v * (1.0f + erff(v * 0.70710678118654752f));
}

/* ------------------------------------------------------------------ */
/* final: out = BN(fc2 result) + residual x. grid (96, 8, 13)          */
/* ------------------------------------------------------------------ */
__global__ void k_final(const float* __restrict__ x, float* __restrict__ out) {
    const int c = blockIdx.x, b = blockIdx.y;
    const int n = blockIdx.z * 256 + threadIdx.x;
    if (n >= NPTS) return;
    float v = fmaf(g_al[c], g_Z1[(size_t)c * PTOT + b * NPTS + n], g_bt[c]);
    size_t oi = ((size_t)b * 96 + c) * NPTS + n;
    out[oi] = v + x[oi];
}

/* ------------------------------------------------------------------ */
extern "C" void kernel_launch(void* const* d_in, const int* in_sizes, int n_in,
                              void* d_out, int out_size) {
    const float* x      = (const float*)d_in[0];
    const float* fc1_w  = (const float*)d_in[1];
    const float* fc1_b  = (const float*)d_in[2];
    const float* fc1_g  = (const float*)d_in[3];
    const float* fc1_be = (const float*)d_in[4];
    const float* g1_w   = (const float*)d_in[5];
    const float* g1_b   = (const float*)d_in[6];
    const float* g1_g   = (const float*)d_in[7];
    const float* g1_be  = (const float*)d_in[8];
    const float* g2_w   = (const float*)d_in[9];
    const float* g2_b   = (const float*)d_in[10];
    const float* g2_g   = (const float*)d_in[11];
    const float* g2_be  = (const float*)d_in[12];
    const float* fc2_w  = (const float*)d_in[13];
    const float* fc2_b  = (const float*)d_in[14];
    const float* fc2_g  = (const float*)d_in[15];
    const float* fc2_be = (const float*)d_in[16];
    float* out = (float*)d_out;

    void *pZ1, *pZ2, *pY, *pY2;
    cudaGetSymbolAddress(&pZ1, g_Z1);
    cudaGetSymbolAddress(&pZ2, g_Z2);
    cudaGetSymbolAddress(&pY,  g_Y);
    cudaGetSymbolAddress(&pY2, g_Y2);

    cudaFuncSetAttribute(k_fc1,       cudaFuncAttributeMaxDynamicSharedMemorySize, 61440);
    cudaFuncSetAttribute(k_knn,       cudaFuncAttributeMaxDynamicSharedMemorySize, 108800);
    cudaFuncSetAttribute(k_gemm<192>, cudaFuncAttributeMaxDynamicSharedMemorySize, 49152);
    cudaFuncSetAttribute(k_gemm<96>,  cudaFuncAttributeMaxDynamicSharedMemorySize, 30720);

    /* fc1 + BN1 */
    k_fc1<<<392, 256, 61440>>>(x, fc1_w, fc1_b, (float*)pZ1);
    k_stats_part<<<dim3(96, 8), 256>>>((const float*)pZ1);
    k_stats_fin<<<1, 96>>>(fc1_g, fc1_be);
    k_bnnorm<<<98, 256>>>();

    /* KNN + aggregation */
    k_knn<<<dim3(25, 8, 2), 256, 108800>>>();
    k_merge<<<98, 256>>>();
    k_agg<<<dim3(8, 13), 256>>>();

    /* g1: GEMM + BN + GELU */
    k_gemm<192><<<392, 256, 49152>>>((const float*)pY, g1_w, g1_b, (float*)pZ2);
    k_stats_part<<<dim3(192, 8), 256>>>((const float*)pZ2);
    k_stats_fin<<<1, 192>>>(g1_g, g1_be);
    k_bngelu<<<dim3(192, 98), 256>>>((const float*)pZ2, (float*)pY2);

    /* g2: GEMM + BN + GELU */
    k_gemm<192><<<392, 256, 49152>>>((const float*)pY2, g2_w, g2_b, (float*)pZ2);
    k_stats_part<<<dim3(192, 8), 256>>>((const float*)pZ2);
    k_stats_fin<<<1, 192>>>(g2_g, g2_be);
    k_bngelu<<<dim3(192, 98), 256>>>((const float*)pZ2, (float*)pY);

    /* fc2 + BN + residual */
    k_gemm<96><<<392, 256, 30720>>>((const float*)pY, fc2_w, fc2_b, (float*)pZ1);
    k_stats_part<<<dim3(96, 8), 256>>>((const float*)pZ1);
    k_stats_fin<<<1, 96>>>(fc2_g, fc2_be);
    k_final<<<dim3(96, 8, 13), 256>>>(x, out);
}

// round 4
// speedup vs baseline: 1.0127x; 1.0127x over previous
#include <cuda_runtime.h>
#include <math.h>
#include <stdint.h>

#define BATCH 8
#define NPTS  3136
#define PTOT  25088           /* BATCH*NPTS */
#define CA    96
#define CB    192
#define KNN   9
#define NBLK  392             /* PTOT/64 */

/* ------------------------------------------------------------------ */
/* scratch (__device__ globals; allocation is forbidden)               */
/* activations channel-major: buf[c*PTOT + b*NPTS + n]                 */
/* ------------------------------------------------------------------ */
__device__ float g_Z1 [CA*PTOT];   /* fc1 pre-BN; reused for fc2 pre-BN */
__device__ float g_H  [CA*PTOT];
__device__ float g_XN [CA*PTOT];
__device__ float g_sqn[PTOT];
__device__ float g_pv [PTOT*4*KNN];   /* 4 partial top-9 lists per point */
__device__ int   g_pi [PTOT*4*KNN];
__device__ float g_Y  [CB*PTOT];      /* agg out; later g2 post-act in  */
__device__ float g_Z2 [CB*PTOT];      /* g1 pre-BN                      */
__device__ float g_ps [CB*NBLK];
__device__ float g_ps2[CB*NBLK];
__device__ float g_al [CB];
__device__ float g_bt [CB];

/* ---- per-block column stats reduce (16 threads share channels) ---- */
__device__ __forceinline__ void stats_epilogue(float s, float s2, int ch, int pg) {
    #pragma unroll
    for (int o = 8; o > 0; o >>= 1) {
        s  += __shfl_down_sync(0xffffffffu, s,  o, 16);
        s2 += __shfl_down_sync(0xffffffffu, s2, o, 16);
    }
    if (pg == 0) {
        g_ps [ch * NBLK + blockIdx.x] = s;
        g_ps2[ch * NBLK + blockIdx.x] = s2;
    }
}

/* ------------------------------------------------------------------ */
/* fc1: Z1[o][p] = sum_k W[o][k]*x[b][k][n] + b[o]; emits stats        */
/* ------------------------------------------------------------------ */
__global__ __launch_bounds__(256, 2) void k_fc1(const float* __restrict__ x,
                                                const float* __restrict__ W,
                                                const float* __restrict__ bias,
                                                float* __restrict__ Z1) {
    extern __shared__ float sm[];
    float* xs = sm;            /* [96][64] */
    float* ws = sm + 96 * 64;  /* [96][96] natural layout */
    const int t  = threadIdx.x;
    const int p0 = blockIdx.x * 64;
    const int b  = p0 / NPTS;
    const int n0 = p0 - b * NPTS;

    for (int i = t; i < 96 * 64; i += 256) {
        int k = i >> 6, c = i & 63;
        xs[i] = x[(size_t)(b * CA + k) * NPTS + n0 + c];
    }
    for (int i = t; i < 96 * 96; i += 256) ws[i] = W[i];
    __syncthreads();

    const int og = t >> 4, pg = t & 15;
    float acc[6][4];
    #pragma unroll
    for (int i = 0; i < 6; ++i) {
        float bb = bias[og * 6 + i];
        #pragma unroll
        for (int j = 0; j < 4; ++j) acc[i][j] = bb;
    }
    #pragma unroll 6
    for (int k = 0; k < 96; ++k) {
        float4 xv = *(const float4*)&xs[k * 64 + pg * 4];
        #pragma unroll
        for (int i = 0; i < 6; ++i) {
            float w = ws[(og * 6 + i) * 96 + k];
            acc[i][0] = fmaf(w, xv.x, acc[i][0]);
            acc[i][1] = fmaf(w, xv.y, acc[i][1]);
            acc[i][2] = fmaf(w, xv.z, acc[i][2]);
            acc[i][3] = fmaf(w, xv.w, acc[i][3]);
        }
    }
    #pragma unroll
    for (int i = 0; i < 6; ++i) {
        float4 v = make_float4(acc[i][0], acc[i][1], acc[i][2], acc[i][3]);
        *(float4*)&Z1[(size_t)(og * 6 + i) * PTOT + p0 + pg * 4] = v;
        float s  = acc[i][0] + acc[i][1] + acc[i][2] + acc[i][3];
        float s2 = acc[i][0]*acc[i][0] + acc[i][1]*acc[i][1]
                 + acc[i][2]*acc[i][2] + acc[i][3]*acc[i][3];
        stats_epilogue(s, s2, og * 6 + i, pg);
    }
}

/* ------------------------------------------------------------------ */
/* finalize BN affine from per-block partials. grid NC, block 128      */
/* ------------------------------------------------------------------ */
__global__ void k_stats_fin(const float* __restrict__ gam,
                            const float* __restrict__ bet) {
    __shared__ float ss[128], ss2[128];
    const int c = blockIdx.x, t = threadIdx.x;
    float s = 0.f, s2 = 0.f;
    for (int b = t; b < NBLK; b += 128) {
        s += g_ps[c * NBLK + b]; s2 += g_ps2[c * NBLK + b];
    }
    ss[t] = s; ss2[t] = s2;
    __syncthreads();
    for (int o = 64; o > 0; o >>= 1) {
        if (t < o) { ss[t] += ss[t + o]; ss2[t] += ss2[t + o]; }
        __syncthreads();
    }
    if (t == 0) {
        const float inv = 1.0f / (float)PTOT;
        float m = ss[0] * inv;
        float v = fmaxf(ss2[0] * inv - m * m, 0.f);
        float a = gam[c] / sqrtf(v + 1e-5f);
        g_al[c] = a;
        g_bt[c] = bet[c] - m * a;
    }
}

/* ------------------------------------------------------------------ */
/* BN1 apply -> H; L2 normalize -> XN; squared norm                    */
/* ------------------------------------------------------------------ */
__global__ __launch_bounds__(256) void k_bnnorm() {
    __shared__ float sa[96], sb[96];
    const int t = threadIdx.x;
    if (t < 96) { sa[t] = g_al[t]; sb[t] = g_bt[t]; }
    __syncthreads();
    const int p = blockIdx.x * 256 + t;
    float a0=0.f,a1=0.f,a2=0.f,a3=0.f,a4=0.f,a5=0.f,a6=0.f,a7=0.f;
    #pragma unroll
    for (int c = 0; c < 96; c += 8) {
        float h0 = fmaf(sa[c+0], g_Z1[(size_t)(c+0)*PTOT + p], sb[c+0]);
        float h1 = fmaf(sa[c+1], g_Z1[(size_t)(c+1)*PTOT + p], sb[c+1]);
        float h2 = fmaf(sa[c+2], g_Z1[(size_t)(c+2)*PTOT + p], sb[c+2]);
        float h3 = fmaf(sa[c+3], g_Z1[(size_t)(c+3)*PTOT + p], sb[c+3]);
        float h4 = fmaf(sa[c+4], g_Z1[(size_t)(c+4)*PTOT + p], sb[c+4]);
        float h5 = fmaf(sa[c+5], g_Z1[(size_t)(c+5)*PTOT + p], sb[c+5]);
        float h6 = fmaf(sa[c+6], g_Z1[(size_t)(c+6)*PTOT + p], sb[c+6]);
        float h7 = fmaf(sa[c+7], g_Z1[(size_t)(c+7)*PTOT + p], sb[c+7]);
        a0 += h0*h0; a1 += h1*h1; a2 += h2*h2; a3 += h3*h3;
        a4 += h4*h4; a5 += h5*h5; a6 += h6*h6; a7 += h7*h7;
    }
    float s = ((a0+a1)+(a2+a3))+((a4+a5)+(a6+a7));
    const float rinv = 1.0f / fmaxf(sqrtf(s), 1e-12f);
    float s2 = 0.f;
    #pragma unroll 8
    for (int c = 0; c < 96; ++c) {
        float h = fmaf(sa[c], g_Z1[(size_t)c*PTOT + p], sb[c]);
        g_H[(size_t)c*PTOT + p] = h;
        float xn = h * rinv;
        g_XN[(size_t)c*PTOT + p] = xn;
        s2 += xn * xn;
    }
    g_sqn[p] = s2;
}

/* ------------------------------------------------------------------ */
/* KNN: fused Gram + distributed top-9. grid (25, 8, 2), block 256     */
/* scores precomputed in gram epilogue; selection = load+compare only  */
/* ------------------------------------------------------------------ */
#define QT 128
#define CT 64
#define DP 68
__global__ __launch_bounds__(256, 2) void k_knn() {
    extern __shared__ float sm[];
    float* qs   = sm;               /* [96][QT] */
    float* cs   = qs + 96 * QT;     /* [96][CT] */
    float* dots = cs + 96 * CT;     /* [QT][DP] scores                */
    float* sq   = dots + QT * DP;   /* [CT]                           */

    const int t    = threadIdx.x;
    const int b    = blockIdx.y;
    const int q0   = blockIdx.x * QT;
    const int half = blockIdx.z;
    const int pb   = b * NPTS;

    for (int i = t; i < 96 * QT; i += 256) {
        int k = i >> 7, q = i & (QT - 1);
        int n = q0 + q; if (n >= NPTS) n = NPTS - 1;
        qs[i] = g_XN[(size_t)k * PTOT + pb + n];
    }

    float bv[KNN]; int bi[KNN];
    #pragma unroll
    for (int r = 0; r < KNN; ++r) { bv[r] = 3.4e38f; bi[r] = 0x7fffffff; }

    const int qg = t >> 4, cg = t & 15;
    const int qsel = t & (QT - 1);
    const int chalf = t >> 7;
    const int tile0 = half ? 25 : 0;
    const int tile1 = half ? 49 : 25;

    for (int tile = tile0; tile < tile1; ++tile) {
        const int cbase = tile * CT;
        __syncthreads();   /* selection of previous tile done */
        for (int i = t; i < 96 * CT; i += 256) {
            int k = i >> 6, c = i & 63;
            cs[i] = g_XN[(size_t)k * PTOT + pb + cbase + c];
        }
        if (t < CT) sq[t] = g_sqn[pb + cbase + t];
        __syncthreads();

        /* gram: 8 queries x 4 candidates per thread */
        float acc[8][4];
        #pragma unroll
        for (int i = 0; i < 8; ++i)
            #pragma unroll
            for (int j = 0; j < 4; ++j) acc[i][j] = 0.f;

        #pragma unroll 4
        for (int k = 0; k < 96; ++k) {
            float4 qa = *(const float4*)&qs[k * QT + qg * 8];
            float4 qb = *(const float4*)&qs[k * QT + qg * 8 + 4];
            float4 cv = *(const float4*)&cs[k * CT + cg * 4];
            float qv[8] = {qa.x, qa.y, qa.z, qa.w, qb.x, qb.y, qb.z, qb.w};
            float cw[4] = {cv.x, cv.y, cv.z, cv.w};
            #pragma unroll
            for (int i = 0; i < 8; ++i)
                #pragma unroll
                for (int j = 0; j < 4; ++j)
                    acc[i][j] = fmaf(qv[i], cw[j], acc[i][j]);
        }
        const float4 sqv = *(const float4*)&sq[cg * 4];
        #pragma unroll
        for (int i = 0; i < 8; ++i) {
            float4 v;
            v.x = fmaf(-2.f, acc[i][0], sqv.x);
            v.y = fmaf(-2.f, acc[i][1], sqv.y);
            v.z = fmaf(-2.f, acc[i][2], sqv.z);
            v.w = fmaf(-2.f, acc[i][3], sqv.w);
            *(float4*)&dots[(qg * 8 + i) * DP + cg * 4] = v;
        }
        __syncthreads();

        /* selection: 256 threads; thread = (query, candidate half of 32) */
        {
            const float* drow = dots + qsel * DP + chalf * 32;
            const int jb0 = cbase + chalf * 32;
            #pragma unroll
            for (int c4 = 0; c4 < 8; ++c4) {
                float4 v = *(const float4*)&drow[c4 * 4];
                float sv[4] = {v.x, v.y, v.z, v.w};
                #pragma unroll
                for (int u = 0; u < 4; ++u) {
                    float s = sv[u];
                    int   j = jb0 + c4 * 4 + u;
                    if (s < bv[8] || (s == bv[8] && j < bi[8])) {
                        bv[8] = s; bi[8] = j;
                        #pragma unroll
                        for (int r = 8; r > 0; --r) {
                            bool sw = (bv[r] < bv[r-1]) ||
                                      (bv[r] == bv[r-1] && bi[r] < bi[r-1]);
                            if (sw) {
                                float tv = bv[r]; bv[r] = bv[r-1]; bv[r-1] = tv;
                                int   ti = bi[r]; bi[r] = bi[r-1]; bi[r-1] = ti;
                            }
                        }
                    }
                }
            }
        }
    }

    if (q0 + qsel < NPTS) {
        size_t base = (((size_t)(pb + q0 + qsel) * 2 + half) * 2 + chalf) * KNN;
        #pragma unroll
        for (int r = 0; r < KNN; ++r) { g_pv[base + r] = bv[r]; g_pi[base + r] = bi[r]; }
    }
}

/* ------------------------------------------------------------------ */
/* merge 4 partial lists + max-relative aggregation + interleave       */
/* grid 392 (64 points each), block 256 = 64 pts x 4 channel groups    */
/* ------------------------------------------------------------------ */
__global__ __launch_bounds__(256) void k_agg() {
    __shared__ float sv[64 * 36];
    __shared__ int   sj[64 * 36];
    __shared__ int   snb[64 * KNN];
    const int t   = threadIdx.x;
    const int blk = blockIdx.x;
    const int b   = blk / 49;
    const int n0  = (blk - b * 49) * 64;
    const int gp0 = b * NPTS + n0;

    for (int i = t; i < 64 * 36; i += 256) {
        sv[i] = g_pv[(size_t)gp0 * 36 + i];
        sj[i] = g_pi[(size_t)gp0 * 36 + i];
    }
    __syncthreads();

    if (t < 64) {
        const float* lv = sv + t * 36;
        const int*   lj = sj + t * 36;
        int ptr[4] = {0, 0, 0, 0};
        #pragma unroll
        for (int r = 0; r < KNN; ++r) {
            float bvv = lv[0 * 9 + ptr[0]]; int bj = lj[0 * 9 + ptr[0]]; int bl = 0;
            #pragma unroll
            for (int l = 1; l < 4; ++l) {
                float cv = lv[l * 9 + ptr[l]]; int cj = lj[l * 9 + ptr[l]];
                if (cv < bvv || (cv == bvv && cj < bj)) { bvv = cv; bj = cj; bl = l; }
            }
            snb[t * KNN + r] = bj;
            ptr[bl]++;
        }
    }
    __syncthreads();

    const int pidx = t & 63;
    const int cg   = t >> 6;
    const int gp   = gp0 + pidx;
    int nb[KNN];
    #pragma unroll
    for (int r = 0; r < KNN; ++r) nb[r] = b * NPTS + snb[pidx * KNN + r];

    #pragma unroll 2
    for (int i = 0; i < 24; ++i) {
        int c = cg + i * 4;
        const float* Hr = g_H + (size_t)c * PTOT;
        float hc = Hr[gp];
        float m0 = Hr[nb[0]], m1 = Hr[nb[1]], m2 = Hr[nb[2]];
        float m3 = Hr[nb[3]], m4 = Hr[nb[4]], m5 = Hr[nb[5]];
        float m6 = Hr[nb[6]], m7 = Hr[nb[7]], m8 = Hr[nb[8]];
        float m = fmaxf(fmaxf(fmaxf(fmaxf(m0,m1),fmaxf(m2,m3)),
                              fmaxf(fmaxf(m4,m5),fmaxf(m6,m7))), m8);
        g_Y[(size_t)(2*c)   * PTOT + gp] = hc;
        g_Y[(size_t)(2*c+1) * PTOT + gp] = m - hc;
    }
}

/* ------------------------------------------------------------------ */
/* GEMM K=192: OUT[o][p] = sum_c W[o][c]*act(IN[c][p]) + b[o]          */
/* ACT: apply BN (g_al/g_bt) + exact GELU on load. Emits stats.        */
/* ------------------------------------------------------------------ */
template<int NCO, bool ACT>
__global__ __launch_bounds__(256, 2) void k_gemm(const float* __restrict__ IN,
                                                 const float* __restrict__ W,
                                                 const float* __restrict__ bias,
                                                 float* __restrict__ OUT) {
    extern __shared__ float sm[];
    float* ys = sm;            /* [48][64]  */
    float* ws = ys + 48 * 64;  /* [NCO][48] */
    const int NO = NCO / 16;
    const int t  = threadIdx.x;
    const int p0 = blockIdx.x * 64;
    const int og = t >> 4, pg = t & 15;

    float acc[NO][4];
    #pragma unroll
    for (int i = 0; i < NO; ++i) {
        float bb = bias[og * NO + i];
        #pragma unroll
        for (int j = 0; j < 4; ++j) acc[i][j] = bb;
    }
    for (int kc = 0; kc < 4; ++kc) {
        __syncthreads();
        for (int i = t; i < 48 * 64; i += 256) {
            int k = i >> 6, c = i & 63;
            int ch = kc * 48 + k;
            float v = IN[(size_t)ch * PTOT + p0 + c];
            if (ACT) {
                v = fmaf(g_al[ch], v, g_bt[ch]);
                v = 0.5f * v * (1.0f + erff(v * 0.70710678118654752f));
            }
            ys[i] = v;
        }
        for (int i = t; i < NCO * 48; i += 256) {
            int o = i / 48, k = i - o * 48;
            ws[i] = W[o * 192 + kc * 48 + k];
        }
        __syncthreads();
        #pragma unroll 4
        for (int k = 0; k < 48; ++k) {
            float4 yv = *(const float4*)&ys[k * 64 + pg * 4];
            #pragma unroll
            for (int i = 0; i < NO; ++i) {
                float w = ws[(og * NO + i) * 48 + k];
                acc[i][0] = fmaf(w, yv.x, acc[i][0]);
                acc[i][1] = fmaf(w, yv.y, acc[i][1]);
                acc[i][2] = fmaf(w, yv.z, acc[i][2]);
                acc[i][3] = fmaf(w, yv.w, acc[i][3]);
            }
        }
    }
    #pragma unroll
    for (int i = 0; i < NO; ++i) {
        float4 v = make_float4(acc[i][0], acc[i][1], acc[i][2], acc[i][3]);
        *(float4*)&OUT[(size_t)(og * NO + i) * PTOT + p0 + pg * 4] = v;
        float s  = acc[i][0] + acc[i][1] + acc[i][2] + acc[i][3];
        float s2 = acc[i][0]*acc[i][0] + acc[i][1]*acc[i][1]
                 + acc[i][2]*acc[i][2] + acc[i][3]*acc[i][3];
        stats_epilogue(s, s2, og * NO + i, pg);
    }
}

/* ------------------------------------------------------------------ */
/* final: out = BN(fc2 pre-act) + residual x (vectorized float4)       */
/* grid (96, 8, 4), block 196                                          */
/* ------------------------------------------------------------------ */
__global__ void k_final(const float* __restrict__ x, float* __restrict__ out) {
    const int c = blockIdx.x, b = blockIdx.y;
    const int q = blockIdx.z * 196 + threadIdx.x;    /* 784 float4 per row */
    const float a = g_al[c], be = g_bt[c];
    const size_t base = ((size_t)b * CA + c) * NPTS;   /* == out layout row */
    const size_t zrow = (size_t)c * PTOT + b * NPTS;
    float4 z = *(const float4*)&g_Z1[zrow + q * 4];
    float4 r = *(const float4*)&x[base + q * 4];
    float4 o;
    o.x = fmaf(a, z.x, be) + r.x;
    o.y = fmaf(a, z.y, be) + r.y;
    o.z = fmaf(a, z.z, be) + r.z;
    o.w = fmaf(a, z.w, be) + r.w;
    *(float4*)&out[base + q * 4] = o;
}

/* ------------------------------------------------------------------ */
extern "C" void kernel_launch(void* const* d_in, const int* in_sizes, int n_in,
                              void* d_out, int out_size) {
    const float* x      = (const float*)d_in[0];
    const float* fc1_w  = (const float*)d_in[1];
    const float* fc1_b  = (const float*)d_in[2];
    const float* fc1_g  = (const float*)d_in[3];
    const float* fc1_be = (const float*)d_in[4];
    const float* g1_w   = (const float*)d_in[5];
    const float* g1_b   = (const float*)d_in[6];
    const float* g1_g   = (const float*)d_in[7];
    const float* g1_be  = (const float*)d_in[8];
    const float* g2_w   = (const float*)d_in[9];
    const float* g2_b   = (const float*)d_in[10];
    const float* g2_g   = (const float*)d_in[11];
    const float* g2_be  = (const float*)d_in[12];
    const float* fc2_w  = (const float*)d_in[13];
    const float* fc2_b  = (const float*)d_in[14];
    const float* fc2_g  = (const float*)d_in[15];
    const float* fc2_be = (const float*)d_in[16];
    float* out = (float*)d_out;

    void *pZ1, *pZ2, *pY;
    cudaGetSymbolAddress(&pZ1, g_Z1);
    cudaGetSymbolAddress(&pZ2, g_Z2);
    cudaGetSymbolAddress(&pY,  g_Y);

    cudaFuncSetAttribute(k_fc1,            cudaFuncAttributeMaxDynamicSharedMemorySize, 61440);
    cudaFuncSetAttribute(k_knn,            cudaFuncAttributeMaxDynamicSharedMemorySize, 108800);
    cudaFuncSetAttribute(k_gemm<192,false>,cudaFuncAttributeMaxDynamicSharedMemorySize, 49152);
    cudaFuncSetAttribute(k_gemm<192,true>, cudaFuncAttributeMaxDynamicSharedMemorySize, 49152);
    cudaFuncSetAttribute(k_gemm<96,true>,  cudaFuncAttributeMaxDynamicSharedMemorySize, 30720);

    /* fc1 + BN1 stats (fused) */
    k_fc1<<<NBLK, 256, 61440>>>(x, fc1_w, fc1_b, (float*)pZ1);
    k_stats_fin<<<96, 128>>>(fc1_g, fc1_be);
    k_bnnorm<<<98, 256>>>();

    /* KNN + merge/aggregate */
    k_knn<<<dim3(25, 8, 2), 256, 108800>>>();
    k_agg<<<NBLK, 256>>>();

    /* g1 (raw input) -> Z2, stats fused */
    k_gemm<192,false><<<NBLK, 256, 49152>>>((const float*)pY, g1_w, g1_b, (float*)pZ2);
    k_stats_fin<<<192, 128>>>(g1_g, g1_be);

    /* g2 reads BN+GELU(Z2) on the fly -> Y, stats fused */
    k_gemm<192,true><<<NBLK, 256, 49152>>>((const float*)pZ2, g2_w, g2_b, (float*)pY);
    k_stats_fin<<<192, 128>>>(g2_g, g2_be);

    /* fc2 reads BN+GELU(Y) on the fly -> Z1, stats fused */
    k_gemm<96,true><<<NBLK, 256, 30720>>>((const float*)pY, fc2_w, fc2_b, (float*)pZ1);
    k_stats_fin<<<96, 128>>>(fc2_g, fc2_be);

    /* BN + residual */
    k_final<<<dim3(96, 8, 4), 196>>>(x, out);
}